// round 6
// baseline (speedup 1.0000x reference)
#include <cuda_runtime.h>
#include <cuda_bf16.h>

static constexpr int BATCH = 2048;
static constexpr int NSLOT = 64;
static constexpr int FEAT  = 19;

__device__ float g_partials[BATCH];
__device__ int   g_count = 0;   // self-resetting -> graph-replay safe

// One CTA per batch, thread i = row i (also column i for the accept step).
// Greedy mutual-best matching == reference scan semantics.
// Row argmax of d = 1-|x-p| is computed as argmin of m = |x-p| (monotone).
__global__ __launch_bounds__(NSLOT) void spotting_match_loss_kernel(
    const float* __restrict__ y_true,
    const float* __restrict__ y_pred,
    float*       __restrict__ out)
{
    const int b = blockIdx.x;
    const int i = threadIdx.x;

    __shared__ alignas(16) float  sp[NSLOT];      // p_j; taken -> 1e30
    __shared__ unsigned long long colkey[NSLOT];  // best proposal per column
    __shared__ int                srow2col[NSLOT];
    __shared__ float              sred[NSLOT];
    __shared__ int                sflag;

    const float* yt = y_true + (size_t)b * NSLOT * FEAT;
    const float* yp = y_pred + (size_t)b * NSLOT * FEAT;

    const float a  = yt[i * FEAT + 0];
    const float xi = yt[i * FEAT + 1];

    sp[i]       = yp[i * FEAT + 1];
    colkey[i]   = 0ULL;
    srow2col[i] = -1;    // self-written, self-read before first barrier: OK

    const float4* sp4 = reinterpret_cast<const float4*>(sp);

    #pragma unroll 1
    for (int phase = 0; phase < 2; ++phase) {
        const bool in_phase = (phase == 0) ? (a > 0.5f) : (a <= 0.5f);

        for (;;) {
            const bool active = in_phase && (srow2col[i] < 0);
            // Barrier A: orders prior accept writes + termination test.
            if (__syncthreads_count(active) == 0) break;

            if (active) {
                // 4 contiguous 16-col chains; full unroll; vec4 broadcast LDS.
                // Strict '<' ascending + ascending chain merge == jnp.argmax
                // first-occurrence tie-break on d (monotone map d = 1 - m).
                float m0 = 3e38f, m1 = 3e38f, m2 = 3e38f, m3 = 3e38f;
                int   j0 = 0,     j1 = 16,    j2 = 32,    j3 = 48;

                #pragma unroll
                for (int k = 0; k < 4; ++k) {
                    const float4 qa = sp4[k];       // j = 4k   .. 4k+3
                    const float4 qb = sp4[4  + k];  // j = 16+4k..
                    const float4 qc = sp4[8  + k];
                    const float4 qd = sp4[12 + k];

                    float t;
                    t = fabsf(xi - qa.x); if (t < m0) { m0 = t; j0 = 4*k + 0; }
                    t = fabsf(xi - qa.y); if (t < m0) { m0 = t; j0 = 4*k + 1; }
                    t = fabsf(xi - qa.z); if (t < m0) { m0 = t; j0 = 4*k + 2; }
                    t = fabsf(xi - qa.w); if (t < m0) { m0 = t; j0 = 4*k + 3; }

                    t = fabsf(xi - qb.x); if (t < m1) { m1 = t; j1 = 16 + 4*k + 0; }
                    t = fabsf(xi - qb.y); if (t < m1) { m1 = t; j1 = 16 + 4*k + 1; }
                    t = fabsf(xi - qb.z); if (t < m1) { m1 = t; j1 = 16 + 4*k + 2; }
                    t = fabsf(xi - qb.w); if (t < m1) { m1 = t; j1 = 16 + 4*k + 3; }

                    t = fabsf(xi - qc.x); if (t < m2) { m2 = t; j2 = 32 + 4*k + 0; }
                    t = fabsf(xi - qc.y); if (t < m2) { m2 = t; j2 = 32 + 4*k + 1; }
                    t = fabsf(xi - qc.z); if (t < m2) { m2 = t; j2 = 32 + 4*k + 2; }
                    t = fabsf(xi - qc.w); if (t < m2) { m2 = t; j2 = 32 + 4*k + 3; }

                    t = fabsf(xi - qd.x); if (t < m3) { m3 = t; j3 = 48 + 4*k + 0; }
                    t = fabsf(xi - qd.y); if (t < m3) { m3 = t; j3 = 48 + 4*k + 1; }
                    t = fabsf(xi - qd.z); if (t < m3) { m3 = t; j3 = 48 + 4*k + 2; }
                    t = fabsf(xi - qd.w); if (t < m3) { m3 = t; j3 = 48 + 4*k + 3; }
                }
                // Ascending merge: ties keep lower chain = lower j.
                if (m1 < m0) { m0 = m1; j0 = j1; }
                if (m2 < m0) { m0 = m2; j0 = j2; }
                if (m3 < m0) { m0 = m3; j0 = j3; }

                // Propose: smaller m = better -> invert for atomicMax.
                // m < 1 for a free column, so high field > 0 -> key != 0.
                const unsigned long long key =
                    ((unsigned long long)(0x7fffffffu - __float_as_uint(m0)) << 6) |
                    (unsigned long long)(63 - i);
                atomicMax(&colkey[j0], key);
            }
            __syncthreads();   // Barrier B: proposals visible

            // Column accept (thread i = column i): proposed column takes its
            // best proposer — exactly E = v*A*C (mutual best).
            const unsigned long long k = colkey[i];
            if (k) {
                const int r = 63 - (int)(k & 63ULL);
                srow2col[r] = i;
                sp[i]       = 1e30f;   // remove column
                colkey[i]   = 0ULL;
            }
            // next iteration's __syncthreads_count orders these writes
        }
    }

    // --- Loss of row i against permuted prediction ---
    const int    pi  = srow2col[i];
    const float* ypp = yp + (size_t)pi * FEAT;

    float l;
    {
        const float d1 = xi - ypp[1];
        const float d0 = a  - ypp[0];
        l = a * 5.0f * d1 * d1
          + a * d0 * d0
          + (1.0f - a) * 0.5f * d0 * d0;
        float s2 = 0.0f;
        #pragma unroll
        for (int f = 2; f < FEAT; ++f) {
            const float d = yt[i * FEAT + f] - ypp[f];
            s2 += d * d;
        }
        l += a * s2;
    }

    // Deterministic block tree-reduce
    sred[i] = l;
    __syncthreads();
    #pragma unroll
    for (int off = NSLOT / 2; off > 0; off >>= 1) {
        if (i < off) sred[i] += sred[i + off];
        __syncthreads();
    }

    // Publish partial; last CTA does the fixed-order global reduction.
    if (i == 0) {
        g_partials[b] = sred[0];
        __threadfence();
        const int t = atomicAdd(&g_count, 1);
        sflag = (t == BATCH - 1);
    }
    __syncthreads();

    if (sflag) {
        float v = 0.0f;
        #pragma unroll
        for (int k = 0; k < BATCH / NSLOT; ++k)
            v += g_partials[i + k * NSLOT];   // fixed order per thread
        sred[i] = v;
        __syncthreads();
        #pragma unroll
        for (int off = NSLOT / 2; off > 0; off >>= 1) {
            if (i < off) sred[i] += sred[i + off];
            __syncthreads();
        }
        if (i == 0) {
            out[0]  = sred[0];
            g_count = 0;   // reset for next graph replay
        }
    }
}

extern "C" void kernel_launch(void* const* d_in, const int* in_sizes, int n_in,
                              void* d_out, int out_size)
{
    const float* y_true = (const float*)d_in[0];
    const float* y_pred = (const float*)d_in[1];
    float*       out    = (float*)d_out;

    spotting_match_loss_kernel<<<BATCH, NSLOT>>>(y_true, y_pred, out);
}